// round 4
// baseline (speedup 1.0000x reference)
#include <cuda_runtime.h>
#include <cuda_bf16.h>

// x  : (1, 64, 28, 28) fp32 -> (2 groups o, 32 ch j, 28 n, 28 m)
// w1 : (128, 9),  w2 : (32, 7, 9)
// out: (1, 256, 28, 28), channel = o*128 + c, rolled +1 along height.
//
// t4[o,n,m,i]        = sum_{j,k} x[o*32+j, n, m+k-3] * w2[j,k,i]
// out[o,c,(n+1)%28,m] = sum_i w1[c,i] * t4[o,n,m,i]
//
// Grid: 112 blocks = (og, n, m-half). One wave, ~2x SM coverage vs 56.

#define NTHREADS 256

__global__ __launch_bounds__(NTHREADS)
void fused_unfold_einsum_kernel(const float* __restrict__ x,
                                const float* __restrict__ w1,
                                const float* __restrict__ w2,
                                float* __restrict__ out) {
    __shared__ __align__(16) float xs[32][20];      // 14-wide tile + 3 halo each side
    __shared__ __align__(16) float w2t[9 * 224];    // [i][k*32 + j]
    __shared__ __align__(16) float w1s[128 * 12];   // [c][i], padded to 12
    __shared__ __align__(16) float t4p[2][14 * 12]; // j-half partials, [m][i] padded
    __shared__ __align__(16) float t4s[14 * 12];    // reduced

    const int tid    = threadIdx.x;
    const int b      = blockIdx.x;      // 0..111
    const int og     = b / 56;
    const int r      = b - og * 56;
    const int n      = r >> 1;
    const int mh     = r & 1;
    const int m_base = mh * 14;

    // --- Stage w2 transposed: w2[(j*7+k)*9 + i] -> w2t[i*224 + k*32 + j]
    for (int idx = tid; idx < 9 * 224; idx += NTHREADS) {
        const int i  = idx / 224;
        const int rr = idx - i * 224;   // k*32 + j
        const int kk = rr >> 5;
        const int j  = rr & 31;
        w2t[idx] = w2[(j * 7 + kk) * 9 + i];
    }
    // --- Stage w1 into padded rows
    for (int idx = tid; idx < 128 * 9; idx += NTHREADS) {
        const int c = idx / 9;
        const int i = idx - c * 9;
        w1s[c * 12 + i] = w1[idx];
    }
    // --- Stage x half-row slab with zero halo: cols = m_base-3 .. m_base+16
    for (int idx = tid; idx < 32 * 20; idx += NTHREADS) {
        const int j   = idx / 20;
        const int col = idx - j * 20;
        const int m   = m_base - 3 + col;
        float v = 0.0f;
        if (m >= 0 && m < 28)
            v = x[((og * 32 + j) * 28 + n) * 28 + m];
        xs[j][col] = v;
    }
    __syncthreads();

    // --- t4 partials: thread = (half of j-range, i, m_local). 252 threads.
    if (tid < 252) {
        const int half = (tid >= 126) ? 1 : 0;
        const int t    = tid - half * 126;
        const int i    = t / 14;
        const int ml   = t - i * 14;
        const int jb   = half * 16;
        const float* __restrict__ wrow = &w2t[i * 224 + jb];

        float a0 = 0.f, a1 = 0.f, a2 = 0.f, a3 = 0.f;
        #pragma unroll
        for (int kk = 0; kk < 7; ++kk) {
            const float4* __restrict__ wv =
                reinterpret_cast<const float4*>(wrow + kk * 32);
            #pragma unroll
            for (int jq = 0; jq < 4; ++jq) {
                const float4 w4 = wv[jq];
                const int j = jb + jq * 4;
                a0 = fmaf(xs[j + 0][ml + kk], w4.x, a0);
                a1 = fmaf(xs[j + 1][ml + kk], w4.y, a1);
                a2 = fmaf(xs[j + 2][ml + kk], w4.z, a2);
                a3 = fmaf(xs[j + 3][ml + kk], w4.w, a3);
            }
        }
        t4p[half][ml * 12 + i] = (a0 + a1) + (a2 + a3);
    }
    __syncthreads();

    // --- Reduce the two j-halves: 168 floats = 42 float4 adds.
    if (tid < 42) {
        const float4 u = reinterpret_cast<const float4*>(t4p[0])[tid];
        const float4 v = reinterpret_cast<const float4*>(t4p[1])[tid];
        reinterpret_cast<float4*>(t4s)[tid] =
            make_float4(u.x + v.x, u.y + v.y, u.z + v.z, u.w + v.w);
    }
    __syncthreads();

    // --- Phase 2: thread = (c, m-segment). w1 row loaded once per thread.
    const int nout = (n + 1) % 28;          // roll(+1, height)
    const int c    = tid & 127;
    const int mseg = tid >> 7;              // 0 or 1 -> m in [0,7) or [7,14)
    const float4* __restrict__ w1v = reinterpret_cast<const float4*>(&w1s[c * 12]);
    const float4 b0 = w1v[0], b1 = w1v[1], b2 = w1v[2];
    float* __restrict__ outp =
        &out[((og * 128 + c) * 28 + nout) * 28 + m_base + mseg * 7];

    #pragma unroll
    for (int q = 0; q < 7; ++q) {
        const int m = mseg * 7 + q;
        const float4* __restrict__ tv = reinterpret_cast<const float4*>(&t4s[m * 12]);
        const float4 a0 = tv[0], a1 = tv[1], a2 = tv[2];
        float acc = a0.x * b0.x;
        acc = fmaf(a0.y, b0.y, acc);
        acc = fmaf(a0.z, b0.z, acc);
        acc = fmaf(a0.w, b0.w, acc);
        acc = fmaf(a1.x, b1.x, acc);
        acc = fmaf(a1.y, b1.y, acc);
        acc = fmaf(a1.z, b1.z, acc);
        acc = fmaf(a1.w, b1.w, acc);
        acc = fmaf(a2.x, b2.x, acc);    // i = 8; padding lanes unused
        outp[q] = acc;
    }
}

extern "C" void kernel_launch(void* const* d_in, const int* in_sizes, int n_in,
                              void* d_out, int out_size) {
    const float* x  = (const float*)d_in[0];
    const float* w1 = (const float*)d_in[1];
    const float* w2 = (const float*)d_in[2];
    float* out = (float*)d_out;
    (void)in_sizes; (void)n_in; (void)out_size;

    fused_unfold_einsum_kernel<<<112, NTHREADS>>>(x, w1, w2, out);
}

// round 5
// speedup vs baseline: 1.0308x; 1.0308x over previous
#include <cuda_runtime.h>
#include <cuda_bf16.h>

// x  : (1, 64, 28, 28) fp32 -> (2 groups o, 32 ch j, 28 n, 28 m)
// w1 : (128, 9),  w2 : (32, 7, 9)
// out: (1, 256, 28, 28), channel = o*128 + c, rolled +1 along height.
//
// t4[o,n,m,i]         = sum_{j,k} x[o*32+j, n, m+k-3] * w2[j,k,i]
// out[o,c,(n+1)%28,m] = sum_i w1[c,i] * t4[o,n,m,i]
//
// Grid: 56 blocks = (og, n). R1 structure (best measured), vectorized inner loops.

#define NTHREADS 256

__global__ __launch_bounds__(NTHREADS)
void fused_unfold_einsum_kernel(const float* __restrict__ x,
                                const float* __restrict__ w1,
                                const float* __restrict__ w2,
                                float* __restrict__ out) {
    // x transposed: [mm][j], mm = m+3 in [0,34), row stride 36 floats (144B).
    // 36 % 32 == 4 banks -> consecutive-mm lanes phase onto distinct banks.
    __shared__ __align__(16) float xs_t[34 * 36];
    __shared__ __align__(16) float w2t[9 * 224];   // [i][k*32 + j]
    __shared__ __align__(16) float w1s[128 * 12];  // [c][i], padded 9->12
    __shared__ __align__(16) float t4s[28 * 12];   // [m][i], padded 9->12

    const int tid = threadIdx.x;
    const int b   = blockIdx.x;     // 0..55
    const int og  = b / 28;
    const int n   = b % 28;

    // --- Stage w2 transposed: w2[(j*7+k)*9 + i] -> w2t[i*224 + k*32 + j]
    for (int idx = tid; idx < 9 * 224; idx += NTHREADS) {
        const int i  = idx / 224;
        const int rr = idx - i * 224;   // k*32 + j
        const int kk = rr >> 5;
        const int j  = rr & 31;
        w2t[idx] = w2[(j * 7 + kk) * 9 + i];
    }
    // --- Stage w1 into padded rows
    for (int idx = tid; idx < 128 * 9; idx += NTHREADS) {
        const int c = idx / 9;
        const int i = idx - c * 9;
        w1s[c * 12 + i] = w1[idx];
    }
    // --- Stage x transposed with zero halo: xs_t[mm][j] = x[og*32+j, n, mm-3]
    for (int idx = tid; idx < 34 * 32; idx += NTHREADS) {
        const int mm = idx >> 5;        // 0..33
        const int j  = idx & 31;
        const int m  = mm - 3;
        float v = 0.0f;
        if (m >= 0 && m < 28)
            v = x[((og * 32 + j) * 28 + n) * 28 + m];
        xs_t[mm * 36 + j] = v;
    }
    __syncthreads();

    // --- t4: thread = (i, m). Both operands via LDS.128:
    //     x lanes (consecutive m) conflict-free, w lanes broadcast (i ~uniform).
    if (tid < 252) {
        const int i = tid / 28;
        const int m = tid - i * 28;
        const float* __restrict__ wrow = &w2t[i * 224];

        float a0 = 0.f, a1 = 0.f, a2 = 0.f, a3 = 0.f;
        #pragma unroll
        for (int kk = 0; kk < 7; ++kk) {
            const float4* __restrict__ xv =
                reinterpret_cast<const float4*>(&xs_t[(m + kk) * 36]);
            const float4* __restrict__ wv =
                reinterpret_cast<const float4*>(wrow + kk * 32);
            #pragma unroll
            for (int jq = 0; jq < 8; ++jq) {
                const float4 xx = xv[jq];
                const float4 ww = wv[jq];
                a0 = fmaf(xx.x, ww.x, a0);
                a1 = fmaf(xx.y, ww.y, a1);
                a2 = fmaf(xx.z, ww.z, a2);
                a3 = fmaf(xx.w, ww.w, a3);
            }
        }
        t4s[m * 12 + i] = (a0 + a1) + (a2 + a3);
    }
    __syncthreads();

    // --- Phase 2: t5 + roll fused into store index. float4 LDS, coalesced STG.
    const int nout = (n + 1) % 28;      // roll(+1, height)
    #pragma unroll
    for (int it = 0; it < 14; ++it) {
        const int idx = tid + it * NTHREADS;    // 0..3583
        const int c = idx / 28;
        const int m = idx - c * 28;
        const float4* __restrict__ tv  = reinterpret_cast<const float4*>(&t4s[m * 12]);
        const float4* __restrict__ w1v = reinterpret_cast<const float4*>(&w1s[c * 12]);
        const float4 a0 = tv[0],  a1 = tv[1],  a2 = tv[2];
        const float4 b0 = w1v[0], b1 = w1v[1], b2 = w1v[2];
        float acc = a0.x * b0.x;
        acc = fmaf(a0.y, b0.y, acc);
        acc = fmaf(a0.z, b0.z, acc);
        acc = fmaf(a0.w, b0.w, acc);
        acc = fmaf(a1.x, b1.x, acc);
        acc = fmaf(a1.y, b1.y, acc);
        acc = fmaf(a1.z, b1.z, acc);
        acc = fmaf(a1.w, b1.w, acc);
        acc = fmaf(a2.x, b2.x, acc);    // i = 8; padding lanes unused
        out[((og * 128 + c) * 28 + nout) * 28 + m] = acc;
    }
}

extern "C" void kernel_launch(void* const* d_in, const int* in_sizes, int n_in,
                              void* d_out, int out_size) {
    const float* x  = (const float*)d_in[0];
    const float* w1 = (const float*)d_in[1];
    const float* w2 = (const float*)d_in[2];
    float* out = (float*)d_out;
    (void)in_sizes; (void)n_in; (void)out_size;

    fused_unfold_einsum_kernel<<<56, NTHREADS>>>(x, w1, w2, out);
}

// round 6
// speedup vs baseline: 1.2885x; 1.2500x over previous
#include <cuda_runtime.h>
#include <cuda_bf16.h>

// x  : (1, 64, 28, 28) fp32 -> (2 groups o, 32 ch j, 28 n, 28 m)
// w1 : (128, 9),  w2 : (32, 7, 9)
// out: (1, 256, 28, 28), channel = o*128 + c, rolled +1 along height.
//
// t4[o,n,m,i]         = sum_{j,k} x[o*32+j, n, m+k-3] * w2[j,k,i]
// out[o,c,(n+1)%28,m] = sum_i w1[c,i] * t4[o,n,m,i]
//
// R1 structure verbatim (best measured: 8.4us), single delta: t4 uses two
// accumulators (j<16 / j>=16) to halve the serial FMA chain. Same loads,
// same order, same instruction count.

#define NTHREADS 256

__global__ __launch_bounds__(NTHREADS)
void fused_unfold_einsum_kernel(const float* __restrict__ x,
                                const float* __restrict__ w1,
                                const float* __restrict__ w2,
                                float* __restrict__ out) {
    __shared__ float xs[32][34];        // padded width: mm = m+3 in [0,34)
    __shared__ float w2t[9 * 32 * 7];   // transposed: [i][j*7+k]
    __shared__ float w1s[128 * 9];      // [c][i]
    __shared__ float t4s[28 * 9];       // [m][i]

    const int tid = threadIdx.x;
    const int b   = blockIdx.x;         // 0..55
    const int og  = b / 28;             // group 0/1
    const int n   = b % 28;             // input height row

    // --- Stage w2 transposed: w2[(j*7+k)*9 + i] -> w2t[i*224 + j*7 + k]
    #pragma unroll
    for (int idx = tid; idx < 9 * 224; idx += NTHREADS) {
        const int i = idx / 224;
        const int r = idx - i * 224;    // j*7 + k
        w2t[idx] = w2[r * 9 + i];
    }
    // --- Stage w1
    #pragma unroll
    for (int idx = tid; idx < 128 * 9; idx += NTHREADS) {
        w1s[idx] = w1[idx];
    }
    // --- Stage x row slab with zero halo
    #pragma unroll
    for (int idx = tid; idx < 32 * 34; idx += NTHREADS) {
        const int j  = idx / 34;
        const int mm = idx - j * 34;
        const int m  = mm - 3;
        float v = 0.0f;
        if (m >= 0 && m < 28)
            v = x[((og * 32 + j) * 28 + n) * 28 + m];
        xs[j][mm] = v;
    }
    __syncthreads();

    // --- t4: thread = (i, m). i = tid/28 keeps warps ~uniform in i:
    //     w2t reads broadcast across the warp, xs reads consecutive m.
    if (tid < 252) {
        const int i = tid / 28;
        const int m = tid - i * 28;
        const float* __restrict__ wrow = &w2t[i * 224];
        float acc_lo = 0.0f;
        float acc_hi = 0.0f;
        #pragma unroll
        for (int j = 0; j < 16; ++j) {
            #pragma unroll
            for (int k = 0; k < 7; ++k) {
                acc_lo = fmaf(xs[j][m + k], wrow[j * 7 + k], acc_lo);
            }
        }
        #pragma unroll
        for (int j = 16; j < 32; ++j) {
            #pragma unroll
            for (int k = 0; k < 7; ++k) {
                acc_hi = fmaf(xs[j][m + k], wrow[j * 7 + k], acc_hi);
            }
        }
        t4s[m * 9 + i] = acc_lo + acc_hi;
    }
    __syncthreads();

    // --- t5 + roll fused into the store index.
    const int nout = (n + 1) % 28;      // jnp.roll(y, +1, axis=2)
    #pragma unroll
    for (int idx = tid; idx < 128 * 28; idx += NTHREADS) {
        const int c = idx / 28;
        const int m = idx - c * 28;
        const float* __restrict__ t4m = &t4s[m * 9];
        const float* __restrict__ w1c = &w1s[c * 9];
        float acc = 0.0f;
        #pragma unroll
        for (int i = 0; i < 9; ++i) {
            acc = fmaf(t4m[i], w1c[i], acc);
        }
        out[((og * 128 + c) * 28 + nout) * 28 + m] = acc;
    }
}

extern "C" void kernel_launch(void* const* d_in, const int* in_sizes, int n_in,
                              void* d_out, int out_size) {
    const float* x  = (const float*)d_in[0];
    const float* w1 = (const float*)d_in[1];
    const float* w2 = (const float*)d_in[2];
    float* out = (float*)d_out;
    (void)in_sizes; (void)n_in; (void)out_size;

    fused_unfold_einsum_kernel<<<56, NTHREADS>>>(x, w1, w2, out);
}